// round 8
// baseline (speedup 1.0000x reference)
#include <cuda_runtime.h>
#include <cuda_fp16.h>
#include <cstdint>

// ---------------------------------------------------------------- constants
#define N_ROWS 8192
#define DIMS   2048
#define CHUNK  8
#define TM 128
#define TN 128
#define KC 64                     // K per smem stage (4 mma k-steps of 16)
#define NB (N_ROWS / TM)          // 64
#define NCHUNK (DIMS / KC)        // 32
#define NTILES (NB * (NB + 1) / 2)  // 2080 upper-triangular tiles
#define NSTAGE 3
#define NPERSIST (2 * 148)        // 296 persistent CTAs (2 per SM)

#define TILE_B  (128 * 128)       // 16 KB: 128 rows x 64 fp16 (128B)
#define STAGE_B (2 * TILE_B)      // A, B = 32 KB
#define SMEM_TOTAL (NSTAGE * STAGE_B)  // 96 KB -> 2 CTAs/SM

#define NEG_INF __int_as_float(0xFF800000)

// ---------------------------------------------------------------- scratch
__device__ unsigned long long g_best[N_ROWS];
__device__ float g_dap[N_ROWS];
__device__ __half g_xh[(size_t)N_ROWS * DIMS];

// ---------------------------------------------------------------- helpers
__device__ __forceinline__ uint32_t smem_u32(const void* p) {
    uint32_t a;
    asm("{ .reg .u64 t; cvta.to.shared.u64 t, %1; cvt.u32.u64 %0, t; }" : "=r"(a) : "l"(p));
    return a;
}
__device__ __forceinline__ unsigned long long packCand(float v, unsigned j) {
    unsigned u = __float_as_uint(v);
    u = (u & 0x80000000u) ? ~u : (u | 0x80000000u);
    return ((unsigned long long)u << 32) | (unsigned long long)(0xFFFFFFFFu - j);
}
__device__ __forceinline__ void cpasync16(uint32_t dst, const void* src) {
    asm volatile("cp.async.cg.shared.global [%0], [%1], 16;" :: "r"(dst), "l"(src) : "memory");
}
__device__ __forceinline__ void ldsm_x4(uint32_t* r, uint32_t addr) {
    asm volatile("ldmatrix.sync.aligned.m8n8.x4.shared.b16 {%0,%1,%2,%3}, [%4];"
                 : "=r"(r[0]), "=r"(r[1]), "=r"(r[2]), "=r"(r[3]) : "r"(addr));
}
__device__ __forceinline__ void mma16816(float* d, const uint32_t* a, const uint32_t* b) {
    asm volatile(
        "mma.sync.aligned.m16n8k16.row.col.f32.f16.f16.f32 "
        "{%0,%1,%2,%3}, {%4,%5,%6,%7}, {%8,%9}, {%0,%1,%2,%3};"
        : "+f"(d[0]), "+f"(d[1]), "+f"(d[2]), "+f"(d[3])
        : "r"(a[0]), "r"(a[1]), "r"(a[2]), "r"(a[3]), "r"(b[0]), "r"(b[1]));
}
__device__ __forceinline__ uint32_t swz(int row, int chunk) {
    return (uint32_t)(row * 128 + ((chunk ^ (row & 7)) << 4));
}
__device__ __forceinline__ int triC(int b) { return b * NB - (b * (b - 1)) / 2; }

// ---------------------------------------------------------------- kernel 1: fused prep
__global__ __launch_bounds__(256) void prepKernel(const float* __restrict__ x,
                                                  float* __restrict__ out) {
    const int c = blockIdx.x;                 // 0..1023
    if (threadIdx.x < CHUNK) g_best[c * CHUNK + threadIdx.x] = 0ull;
    if (c == 0 && threadIdx.x == 0) out[0] = 0.0f;

    const float4* base = (const float4*)(x + (size_t)c * CHUNK * DIMS);
    const int D4 = DIMS / 4;

    float acc[CHUNK];
    #pragma unroll
    for (int r = 0; r < CHUNK; r++) acc[r] = 0.0f;

    for (int col = threadIdx.x; col < D4; col += blockDim.x) {
        float4 v[CHUNK];
        float4 m = make_float4(0.f, 0.f, 0.f, 0.f);
        #pragma unroll
        for (int r = 0; r < CHUNK; r++) {
            v[r] = base[r * D4 + col];
            m.x += v[r].x; m.y += v[r].y; m.z += v[r].z; m.w += v[r].w;
        }
        m.x *= 0.125f; m.y *= 0.125f; m.z *= 0.125f; m.w *= 0.125f;
        #pragma unroll
        for (int r = 0; r < CHUNK; r++) {
            acc[r] += fabsf(v[r].x - m.x) + fabsf(v[r].y - m.y)
                    + fabsf(v[r].z - m.z) + fabsf(v[r].w - m.w);
            __half2 p0 = __floats2half2_rn(v[r].x, v[r].y);
            __half2 p1 = __floats2half2_rn(v[r].z, v[r].w);
            uint2 pk;
            pk.x = *(uint32_t*)&p0;
            pk.y = *(uint32_t*)&p1;
            ((uint2*)g_xh)[(size_t)(c * CHUNK + r) * D4 + col] = pk;
        }
    }

    __shared__ float part[CHUNK][8];
    int lane = threadIdx.x & 31, w = threadIdx.x >> 5;
    #pragma unroll
    for (int r = 0; r < CHUNK; r++) {
        float s = acc[r];
        #pragma unroll
        for (int off = 16; off; off >>= 1) s += __shfl_xor_sync(0xFFFFFFFFu, s, off);
        if (lane == 0) part[r][w] = s;
    }
    __syncthreads();
    if (threadIdx.x < CHUNK) {
        float s = 0.f;
        #pragma unroll
        for (int ww = 0; ww < 8; ww++) s += part[threadIdx.x][ww];
        g_dap[c * CHUNK + threadIdx.x] = 0.5f * s * (1.0f / DIMS);
    }
}

// ---------------------------------------------------------------- kernel 2: persistent fp16 HMMA sim + fused argmax
__device__ __forceinline__ void fill_stage(uint32_t sbase, int rowA, int rowB,
                                           int k0, int tid) {
    const __half* srcs[2] = { g_xh + (size_t)rowA * DIMS, g_xh + (size_t)rowB * DIMS };
    #pragma unroll
    for (int o = 0; o < 2; o++) {
        uint32_t base = sbase + o * TILE_B;
        const char* g = (const char*)(srcs[o]) + (size_t)k0 * 2;
        #pragma unroll
        for (int c = tid; c < 1024; c += 256) {
            int row = c >> 3, ch = c & 7;
            cpasync16(base + swz(row, ch), g + (size_t)row * (DIMS * 2) + ch * 16);
        }
    }
}

__global__ __launch_bounds__(256, 2) void simArgmaxMma() {
    extern __shared__ char smem[];
    const uint32_t sb = smem_u32(smem);
    const int tid = threadIdx.x;
    const int lane = tid & 31, warp = tid >> 5;
    const int wr = warp >> 1, wc = warp & 1;   // 4 x 2 warp grid, warp tile 32x64
    const int mi = lane >> 3, r8 = lane & 7;
    const int qrow = lane >> 2;            // 0..7
    const int qcol = (lane & 3) * 2;       // 0,2,4,6

    #pragma unroll 1
    for (int tile = blockIdx.x; tile < NTILES; tile += NPERSIST) {
        // triangular index -> (bi, bj)
        int bi, bj;
        {
            int t = tile;
            float nb5 = NB + 0.5f;
            int b = (int)floorf(nb5 - sqrtf(nb5 * nb5 - 2.0f * (float)t));
            if (b < 0) b = 0;
            if (b > NB - 1) b = NB - 1;
            while (triC(b) > t) b--;
            while (triC(b + 1) <= t) b++;
            bi = b;
            bj = bi + (t - triC(bi));
        }
        const bool diag = (bi == bj);
        const int rowA = bi * TM, rowB = bj * TN;

        float acc[2][8][4];
        #pragma unroll
        for (int mt = 0; mt < 2; mt++)
            #pragma unroll
            for (int nt = 0; nt < 8; nt++)
                #pragma unroll
                for (int e = 0; e < 4; e++) acc[mt][nt][e] = 0.0f;

        // prologue: 2 stages in flight
        fill_stage(sb + 0 * STAGE_B, rowA, rowB, 0, tid);
        asm volatile("cp.async.commit_group;" ::: "memory");
        fill_stage(sb + 1 * STAGE_B, rowA, rowB, KC, tid);
        asm volatile("cp.async.commit_group;" ::: "memory");

        #pragma unroll 1
        for (int t = 0; t < NCHUNK; t++) {
            if (t == NCHUNK - 1) {
                asm volatile("cp.async.wait_group 0;" ::: "memory");
            } else {
                asm volatile("cp.async.wait_group 1;" ::: "memory");
            }
            __syncthreads();

            if (t + 2 < NCHUNK) {
                fill_stage(sb + ((t + 2) % NSTAGE) * STAGE_B, rowA, rowB,
                           (t + 2) * KC, tid);
                asm volatile("cp.async.commit_group;" ::: "memory");
            }

            const uint32_t stg = sb + (t % NSTAGE) * STAGE_B;
            const uint32_t sA = stg;
            const uint32_t sB = stg + TILE_B;

            #pragma unroll
            for (int ks = 0; ks < 4; ks++) {
                const int chunk = ks * 2 + (mi >> 1);
                uint32_t a[2][4], b[8][2];
                #pragma unroll
                for (int mt = 0; mt < 2; mt++) {
                    int row = wr * 32 + mt * 16 + (mi & 1) * 8 + r8;
                    ldsm_x4(a[mt], sA + swz(row, chunk));
                }
                #pragma unroll
                for (int np = 0; np < 4; np++) {
                    int row = wc * 64 + np * 16 + (mi & 1) * 8 + r8;
                    uint32_t tb[4];
                    ldsm_x4(tb, sB + swz(row, chunk));
                    b[2 * np][0] = tb[0]; b[2 * np + 1][0] = tb[1];
                    b[2 * np][1] = tb[2]; b[2 * np + 1][1] = tb[3];
                }
                #pragma unroll
                for (int mt = 0; mt < 2; mt++)
                    #pragma unroll
                    for (int nt = 0; nt < 8; nt++)
                        mma16816(acc[mt][nt], a[mt], b[nt]);
            }
        }

        // ---------------- epilogue ----------------
        __syncthreads();   // smem reuse below (colred overlaps stage 0)

        #pragma unroll
        for (int mt = 0; mt < 2; mt++)
            #pragma unroll
            for (int half = 0; half < 2; half++) {
                const int gi = rowA + wr * 32 + mt * 16 + half * 8 + qrow;
                float bv = NEG_INF;
                unsigned bj_ = 0;
                #pragma unroll
                for (int nt = 0; nt < 8; nt++)
                    #pragma unroll
                    for (int e = 0; e < 2; e++) {
                        const int gj = rowB + wc * 64 + nt * 8 + qcol + e;
                        float v = acc[mt][nt][half * 2 + e];
                        if (diag && ((gi >> 2) == (gj >> 2))) v = NEG_INF;
                        if (v > bv) { bv = v; bj_ = (unsigned)gj; }
                    }
                unsigned long long p = packCand(bv, bj_);
                #pragma unroll
                for (int off = 1; off <= 2; off <<= 1) {
                    unsigned long long q = __shfl_xor_sync(0xFFFFFFFFu, p, off);
                    if (q > p) p = q;
                }
                if ((lane & 3) == 0) atomicMax(&g_best[gi], p);
            }

        if (!diag) {
            unsigned long long* colred = (unsigned long long*)smem;
            #pragma unroll
            for (int nt = 0; nt < 8; nt++)
                #pragma unroll
                for (int e = 0; e < 2; e++) {
                    float bv = NEG_INF;
                    unsigned br = 0;
                    #pragma unroll
                    for (int mt = 0; mt < 2; mt++)
                        #pragma unroll
                        for (int half = 0; half < 2; half++) {
                            const int gi = rowA + wr * 32 + mt * 16 + half * 8 + qrow;
                            float v = acc[mt][nt][half * 2 + e];
                            if (v > bv) { bv = v; br = (unsigned)gi; }
                        }
                    unsigned long long p = packCand(bv, br);
                    #pragma unroll
                    for (int off = 4; off <= 16; off <<= 1) {
                        unsigned long long q = __shfl_xor_sync(0xFFFFFFFFu, p, off);
                        if (q > p) p = q;
                    }
                    if (qrow == 0) {
                        const int lc = wc * 64 + nt * 8 + qcol + e;
                        colred[lc * 4 + wr] = p;
                    }
                }
            __syncthreads();
            if (tid < 128) {
                unsigned long long p = colred[tid * 4];
                #pragma unroll
                for (int w = 1; w < 4; w++) {
                    unsigned long long q = colred[tid * 4 + w];
                    if (q > p) p = q;
                }
                atomicMax(&g_best[rowB + tid], p);
            }
        }

        __syncthreads();   // protect colred/stage smem before next tile's fill
    }
}

// ---------------------------------------------------------------- kernel 3: final
__global__ void finalKernel(const float* __restrict__ x, float* __restrict__ out) {
    const int i = blockIdx.x;
    const unsigned j = 0xFFFFFFFFu - (unsigned)(g_best[i] & 0xFFFFFFFFull);

    const float4* xi = (const float4*)(x + (size_t)i * DIMS);
    const float4* xj = (const float4*)(x + (size_t)j * DIMS);
    const int D4 = DIMS / 4;

    float s = 0.0f;
    for (int c = threadIdx.x; c < D4; c += blockDim.x) {
        float4 a = xi[c];
        float4 b = xj[c];
        s += fabsf(a.x - b.x) + fabsf(a.y - b.y) + fabsf(a.z - b.z) + fabsf(a.w - b.w);
    }

    __shared__ float part[8];
    int lane = threadIdx.x & 31, w = threadIdx.x >> 5;
    #pragma unroll
    for (int off = 16; off; off >>= 1) s += __shfl_xor_sync(0xFFFFFFFFu, s, off);
    if (lane == 0) part[w] = s;
    __syncthreads();
    if (threadIdx.x == 0) {
        float tot = 0.f;
        #pragma unroll
        for (int ww = 0; ww < 8; ww++) tot += part[ww];
        float dan = tot * (1.0f / DIMS);
        atomicAdd(out, 0.125f * g_dap[i] / (dan + 1e-7f));
    }
}

// ----------------------------------------------------------------
extern "C" void kernel_launch(void* const* d_in, const int* in_sizes, int n_in,
                              void* d_out, int out_size) {
    const float* x = (const float*)d_in[0];
    float* out = (float*)d_out;

    cudaFuncSetAttribute(simArgmaxMma, cudaFuncAttributeMaxDynamicSharedMemorySize,
                         SMEM_TOTAL);

    prepKernel<<<N_ROWS / CHUNK, 256>>>(x, out);
    simArgmaxMma<<<NPERSIST, 256, SMEM_TOTAL>>>();
    finalKernel<<<N_ROWS, 256>>>(x, out);
}

// round 10
// speedup vs baseline: 1.2274x; 1.2274x over previous
#include <cuda_runtime.h>
#include <cuda_fp16.h>
#include <cstdint>

// ---------------------------------------------------------------- constants
#define N_ROWS 8192
#define DIMS   2048
#define CHUNK  8
#define TM 128
#define TN 128
#define KC 64                     // K per smem stage (4 mma k-steps of 16)
#define NB (N_ROWS / TM)          // 64
#define NCHUNK (DIMS / KC)        // 32
#define NTILES (NB * (NB + 1) / 2)  // 2080 upper-triangular tiles
#define NSTAGE 3

#define TILE_B  (128 * 128)       // 16 KB: 128 rows x 64 fp16 (128B)
#define STAGE_B (2 * TILE_B)      // A, B = 32 KB
#define SMEM_TOTAL (NSTAGE * STAGE_B)  // 96 KB -> 2 CTAs/SM

#define NEG_INF __int_as_float(0xFF800000)

// ---------------------------------------------------------------- scratch
__device__ unsigned long long g_best[N_ROWS];
__device__ float g_dap[N_ROWS];
__device__ __half g_xh[(size_t)N_ROWS * DIMS];

// ---------------------------------------------------------------- helpers
__device__ __forceinline__ uint32_t smem_u32(const void* p) {
    uint32_t a;
    asm("{ .reg .u64 t; cvta.to.shared.u64 t, %1; cvt.u32.u64 %0, t; }" : "=r"(a) : "l"(p));
    return a;
}
__device__ __forceinline__ unsigned long long packCand(float v, unsigned j) {
    unsigned u = __float_as_uint(v);
    u = (u & 0x80000000u) ? ~u : (u | 0x80000000u);
    return ((unsigned long long)u << 32) | (unsigned long long)(0xFFFFFFFFu - j);
}
__device__ __forceinline__ void cpasync16(uint32_t dst, const void* src) {
    asm volatile("cp.async.cg.shared.global [%0], [%1], 16;" :: "r"(dst), "l"(src) : "memory");
}
__device__ __forceinline__ void ldsm_x4(uint32_t* r, uint32_t addr) {
    asm volatile("ldmatrix.sync.aligned.m8n8.x4.shared.b16 {%0,%1,%2,%3}, [%4];"
                 : "=r"(r[0]), "=r"(r[1]), "=r"(r[2]), "=r"(r[3]) : "r"(addr));
}
// fp16-accumulate mma: d/c are 2 regs (4 halves)
__device__ __forceinline__ void mma16816h(uint32_t* d, const uint32_t* a, const uint32_t* b) {
    asm volatile(
        "mma.sync.aligned.m16n8k16.row.col.f16.f16.f16.f16 "
        "{%0,%1}, {%2,%3,%4,%5}, {%6,%7}, {%0,%1};"
        : "+r"(d[0]), "+r"(d[1])
        : "r"(a[0]), "r"(a[1]), "r"(a[2]), "r"(a[3]), "r"(b[0]), "r"(b[1]));
}
__device__ __forceinline__ uint32_t swz(int row, int chunk) {
    return (uint32_t)(row * 128 + ((chunk ^ (row & 7)) << 4));
}
__device__ __forceinline__ int triC(int b) { return b * NB - (b * (b - 1)) / 2; }

// ---------------------------------------------------------------- kernel 1: fused prep
__global__ __launch_bounds__(256) void prepKernel(const float* __restrict__ x,
                                                  float* __restrict__ out) {
    const int c = blockIdx.x;                 // 0..1023
    if (threadIdx.x < CHUNK) g_best[c * CHUNK + threadIdx.x] = 0ull;
    if (c == 0 && threadIdx.x == 0) out[0] = 0.0f;

    const float4* base = (const float4*)(x + (size_t)c * CHUNK * DIMS);
    const int D4 = DIMS / 4;

    float acc[CHUNK];
    #pragma unroll
    for (int r = 0; r < CHUNK; r++) acc[r] = 0.0f;

    for (int col = threadIdx.x; col < D4; col += blockDim.x) {
        float4 v[CHUNK];
        float4 m = make_float4(0.f, 0.f, 0.f, 0.f);
        #pragma unroll
        for (int r = 0; r < CHUNK; r++) {
            v[r] = base[r * D4 + col];
            m.x += v[r].x; m.y += v[r].y; m.z += v[r].z; m.w += v[r].w;
        }
        m.x *= 0.125f; m.y *= 0.125f; m.z *= 0.125f; m.w *= 0.125f;
        #pragma unroll
        for (int r = 0; r < CHUNK; r++) {
            acc[r] += fabsf(v[r].x - m.x) + fabsf(v[r].y - m.y)
                    + fabsf(v[r].z - m.z) + fabsf(v[r].w - m.w);
            __half2 p0 = __floats2half2_rn(v[r].x, v[r].y);
            __half2 p1 = __floats2half2_rn(v[r].z, v[r].w);
            uint2 pk;
            pk.x = *(uint32_t*)&p0;
            pk.y = *(uint32_t*)&p1;
            ((uint2*)g_xh)[(size_t)(c * CHUNK + r) * D4 + col] = pk;
        }
    }

    __shared__ float part[CHUNK][8];
    int lane = threadIdx.x & 31, w = threadIdx.x >> 5;
    #pragma unroll
    for (int r = 0; r < CHUNK; r++) {
        float s = acc[r];
        #pragma unroll
        for (int off = 16; off; off >>= 1) s += __shfl_xor_sync(0xFFFFFFFFu, s, off);
        if (lane == 0) part[r][w] = s;
    }
    __syncthreads();
    if (threadIdx.x < CHUNK) {
        float s = 0.f;
        #pragma unroll
        for (int ww = 0; ww < 8; ww++) s += part[threadIdx.x][ww];
        g_dap[c * CHUNK + threadIdx.x] = 0.5f * s * (1.0f / DIMS);
    }
}

// ---------------------------------------------------------------- kernel 2: fp16 HMMA (fp16 acc) sim + fused argmax
__device__ __forceinline__ void fill_stage(uint32_t sbase, int rowA, int rowB,
                                           int k0, int tid) {
    const __half* srcs[2] = { g_xh + (size_t)rowA * DIMS, g_xh + (size_t)rowB * DIMS };
    #pragma unroll
    for (int o = 0; o < 2; o++) {
        uint32_t base = sbase + o * TILE_B;
        const char* g = (const char*)(srcs[o]) + (size_t)k0 * 2;
        #pragma unroll
        for (int c = tid; c < 1024; c += 256) {
            int row = c >> 3, ch = c & 7;
            cpasync16(base + swz(row, ch), g + (size_t)row * (DIMS * 2) + ch * 16);
        }
    }
}

__global__ __launch_bounds__(256, 2) void simArgmaxMma() {
    int bi, bj;
    {
        int t = blockIdx.x;
        float nb5 = NB + 0.5f;
        int b = (int)floorf(nb5 - sqrtf(nb5 * nb5 - 2.0f * (float)t));
        if (b < 0) b = 0;
        if (b > NB - 1) b = NB - 1;
        while (triC(b) > t) b--;
        while (triC(b + 1) <= t) b++;
        bi = b;
        bj = bi + (t - triC(bi));
    }
    const bool diag = (bi == bj);

    extern __shared__ char smem[];
    const uint32_t sb = smem_u32(smem);
    const int tid = threadIdx.x;
    const int lane = tid & 31, warp = tid >> 5;
    const int wr = warp >> 1, wc = warp & 1;   // 4 x 2 warp grid, warp tile 32x64

    const int rowA = bi * TM, rowB = bj * TN;

    // fp16 accumulators: [mt][nt] -> 2 regs = rows (qrow, qrow+8) x cols (qcol, qcol+1)
    uint32_t acc[2][8][2];
    #pragma unroll
    for (int mt = 0; mt < 2; mt++)
        #pragma unroll
        for (int nt = 0; nt < 8; nt++) {
            acc[mt][nt][0] = 0u;
            acc[mt][nt][1] = 0u;
        }

    const int mi = lane >> 3, r8 = lane & 7;

    fill_stage(sb + 0 * STAGE_B, rowA, rowB, 0, tid);
    asm volatile("cp.async.commit_group;" ::: "memory");
    fill_stage(sb + 1 * STAGE_B, rowA, rowB, KC, tid);
    asm volatile("cp.async.commit_group;" ::: "memory");

    #pragma unroll 1
    for (int t = 0; t < NCHUNK; t++) {
        if (t == NCHUNK - 1) {
            asm volatile("cp.async.wait_group 0;" ::: "memory");
        } else {
            asm volatile("cp.async.wait_group 1;" ::: "memory");
        }
        __syncthreads();

        if (t + 2 < NCHUNK) {
            fill_stage(sb + ((t + 2) % NSTAGE) * STAGE_B, rowA, rowB, (t + 2) * KC, tid);
            asm volatile("cp.async.commit_group;" ::: "memory");
        }

        const uint32_t stg = sb + (t % NSTAGE) * STAGE_B;
        const uint32_t sA = stg;
        const uint32_t sB = stg + TILE_B;

        #pragma unroll
        for (int ks = 0; ks < 4; ks++) {
            const int chunk = ks * 2 + (mi >> 1);
            uint32_t a[2][4], b[8][2];
            #pragma unroll
            for (int mt = 0; mt < 2; mt++) {
                int row = wr * 32 + mt * 16 + (mi & 1) * 8 + r8;
                ldsm_x4(a[mt], sA + swz(row, chunk));
            }
            #pragma unroll
            for (int np = 0; np < 4; np++) {
                int row = wc * 64 + np * 16 + (mi & 1) * 8 + r8;
                uint32_t tb[4];
                ldsm_x4(tb, sB + swz(row, chunk));
                b[2 * np][0] = tb[0]; b[2 * np + 1][0] = tb[1];
                b[2 * np][1] = tb[2]; b[2 * np + 1][1] = tb[3];
            }
            #pragma unroll
            for (int mt = 0; mt < 2; mt++)
                #pragma unroll
                for (int nt = 0; nt < 8; nt++)
                    mma16816h(acc[mt][nt], a[mt], b[nt]);
        }
    }

    // ---------------- epilogue ----------------
    __syncthreads();   // smem reuse below
    const int qrow = lane >> 2;            // 0..7
    const int qcol = (lane & 3) * 2;       // 0,2,4,6

    #pragma unroll
    for (int mt = 0; mt < 2; mt++)
        #pragma unroll
        for (int half = 0; half < 2; half++) {
            const int gi = rowA + wr * 32 + mt * 16 + half * 8 + qrow;
            float bv = NEG_INF;
            unsigned bj_ = 0;
            #pragma unroll
            for (int nt = 0; nt < 8; nt++) {
                float2 v2 = __half22float2(*(const __half2*)&acc[mt][nt][half]);
                float ve[2] = { v2.x, v2.y };
                #pragma unroll
                for (int e = 0; e < 2; e++) {
                    const int gj = rowB + wc * 64 + nt * 8 + qcol + e;
                    float v = ve[e];
                    if (diag && ((gi >> 2) == (gj >> 2))) v = NEG_INF;
                    if (v > bv) { bv = v; bj_ = (unsigned)gj; }
                }
            }
            unsigned long long p = packCand(bv, bj_);
            #pragma unroll
            for (int off = 1; off <= 2; off <<= 1) {
                unsigned long long q = __shfl_xor_sync(0xFFFFFFFFu, p, off);
                if (q > p) p = q;
            }
            if ((lane & 3) == 0) atomicMax(&g_best[gi], p);
        }

    if (!diag) {
        unsigned long long* colred = (unsigned long long*)smem;   // 128 cols x 4 warpRows
        #pragma unroll
        for (int nt = 0; nt < 8; nt++)
            #pragma unroll
            for (int e = 0; e < 2; e++) {
                float bv = NEG_INF;
                unsigned br = 0;
                #pragma unroll
                for (int mt = 0; mt < 2; mt++)
                    #pragma unroll
                    for (int half = 0; half < 2; half++) {
                        const int gi = rowA + wr * 32 + mt * 16 + half * 8 + qrow;
                        float2 v2 = __half22float2(*(const __half2*)&acc[mt][nt][half]);
                        float v = (e == 0) ? v2.x : v2.y;
                        if (v > bv) { bv = v; br = (unsigned)gi; }
                    }
                unsigned long long p = packCand(bv, br);
                #pragma unroll
                for (int off = 4; off <= 16; off <<= 1) {
                    unsigned long long q = __shfl_xor_sync(0xFFFFFFFFu, p, off);
                    if (q > p) p = q;
                }
                if (qrow == 0) {
                    const int lc = wc * 64 + nt * 8 + qcol + e;
                    colred[lc * 4 + wr] = p;
                }
            }
        __syncthreads();
        if (tid < 128) {
            unsigned long long p = colred[tid * 4];
            #pragma unroll
            for (int w = 1; w < 4; w++) {
                unsigned long long q = colred[tid * 4 + w];
                if (q > p) p = q;
            }
            atomicMax(&g_best[rowB + tid], p);
        }
    }
}

// ---------------------------------------------------------------- kernel 3: final
__global__ void finalKernel(const float* __restrict__ x, float* __restrict__ out) {
    const int i = blockIdx.x;
    const unsigned j = 0xFFFFFFFFu - (unsigned)(g_best[i] & 0xFFFFFFFFull);

    const float4* xi = (const float4*)(x + (size_t)i * DIMS);
    const float4* xj = (const float4*)(x + (size_t)j * DIMS);
    const int D4 = DIMS / 4;

    float s = 0.0f;
    for (int c = threadIdx.x; c < D4; c += blockDim.x) {
        float4 a = xi[c];
        float4 b = xj[c];
        s += fabsf(a.x - b.x) + fabsf(a.y - b.y) + fabsf(a.z - b.z) + fabsf(a.w - b.w);
    }

    __shared__ float part[8];
    int lane = threadIdx.x & 31, w = threadIdx.x >> 5;
    #pragma unroll
    for (int off = 16; off; off >>= 1) s += __shfl_xor_sync(0xFFFFFFFFu, s, off);
    if (lane == 0) part[w] = s;
    __syncthreads();
    if (threadIdx.x == 0) {
        float tot = 0.f;
        #pragma unroll
        for (int ww = 0; ww < 8; ww++) tot += part[ww];
        float dan = tot * (1.0f / DIMS);
        atomicAdd(out, 0.125f * g_dap[i] / (dan + 1e-7f));
    }
}

// ----------------------------------------------------------------
extern "C" void kernel_launch(void* const* d_in, const int* in_sizes, int n_in,
                              void* d_out, int out_size) {
    const float* x = (const float*)d_in[0];
    float* out = (float*)d_out;

    cudaFuncSetAttribute(simArgmaxMma, cudaFuncAttributeMaxDynamicSharedMemorySize,
                         SMEM_TOTAL);

    prepKernel<<<N_ROWS / CHUNK, 256>>>(x, out);
    simArgmaxMma<<<NTILES, 256, SMEM_TOTAL>>>();
    finalKernel<<<N_ROWS, 256>>>(x, out);
}